// round 13
// baseline (speedup 1.0000x reference)
#include <cuda_runtime.h>
#include <math.h>

#define NTHR   640
#define NW     20
#define ROWS   112               // 56 pairs: 16 warps x 3 pairs + 4 warps x 2 pairs
#define NPAIR  56
#define HH     64
#define TENC   256
#define NIn    6
#define XSTR   (TENC * NIn)
#define HPS    65     // H pair-row stride in ull units (odd -> conflict-free)
#define XPS    8      // x pair-row stride in ull units (per-warp region)

typedef unsigned long long ull;

// ---- shared layout (float offsets) ----
#define OFF_WHH0 0                  // 12288
#define OFF_WIH1 12288              // 12288
#define OFF_WHH1 24576              // 12288
#define OFF_WIH0 36864              // 1152 (enc [6][192]) / dec vector [192]
#define OFF_B0I  38016              // 192
#define OFF_B0H  38208
#define OFF_B1I  38400
#define OFF_B1H  38592
#define OFF_H0   38784              // 56*65*2 = 7280
#define OFF_H1   46064              // 7280
#define OFF_X0   53344              // 20 warps * 64 = 1280
#define OFF_X1   54624              // 1280
#define OFF_PREV 55904              // 128 floats (rows)
#define OFF_HW   56032              // 128 : [0..63]=Won, [64..127]=Wcv
#define OFF_HB   56160              // 2
#define SMEM_FLOATS 56162           // ~224.6 KB

__device__ __forceinline__ ull splat(float v) {
    ull r; asm("mov.b64 %0, {%1, %1};" : "=l"(r) : "f"(v)); return r;
}
__device__ __forceinline__ ull pack2(float a, float b) {
    ull r; asm("mov.b64 %0, {%1, %2};" : "=l"(r) : "f"(a), "f"(b)); return r;
}
__device__ __forceinline__ float2 unp(ull v) {
    float2 f; asm("mov.b64 {%0, %1}, %2;" : "=f"(f.x), "=f"(f.y) : "l"(v)); return f;
}
__device__ __forceinline__ void fma2(ull& d, ull a, ull b) {
    asm("fma.rn.f32x2 %0, %1, %2, %0;" : "+l"(d) : "l"(a), "l"(b));
}
__device__ __forceinline__ float sigf(float x) {
    return __fdividef(1.0f, 1.0f + __expf(-x));
}
__device__ __forceinline__ float tanhfast(float x) {
    float e = __expf(2.0f * x);
    return 1.0f - __fdividef(2.0f, e + 1.0f);
}

// transpose [192][64] gmem -> [64][192] smem
__device__ __forceinline__ void loadWT(float* dst, const float* __restrict__ g) {
    for (int i = threadIdx.x; i < 64 * 192; i += NTHR) {
        int k = i / 192, j = i - k * 192;
        dst[i] = g[j * 64 + k];
    }
}

// Accumulate U[pairs][K] @ W[K][192] into thread tile (P pairs x 2 units x 3 gates).
template <int K, int PSTR, int P>
__device__ __forceinline__ void accumK(const float* __restrict__ W,
                                       const ull* __restrict__ Up,
                                       int p0, int jb,
                                       ull aR[P][2], ull aZ[P][2], ull aT[P][2]) {
    const ull* h = Up + p0 * PSTR;
    const float* w = W + jb;
#pragma unroll 2
    for (int k = 0; k < K; k++) {
        ull hv[P];
#pragma unroll
        for (int p = 0; p < P; p++) hv[p] = h[p * PSTR + k];
        float2 wr = *(const float2*)w;
        float2 wz = *(const float2*)(w + 64);
        float2 wn = *(const float2*)(w + 128);
        ull wr0 = splat(wr.x), wr1 = splat(wr.y);
        ull wz0 = splat(wz.x), wz1 = splat(wz.y);
        ull wn0 = splat(wn.x), wn1 = splat(wn.y);
#pragma unroll
        for (int p = 0; p < P; p++) {
            fma2(aR[p][0], hv[p], wr0); fma2(aR[p][1], hv[p], wr1);
            fma2(aZ[p][0], hv[p], wz0); fma2(aZ[p][1], hv[p], wz1);
            fma2(aT[p][0], hv[p], wn0); fma2(aT[p][1], hv[p], wn1);
        }
        w += 192;
    }
}

template <int P>
__device__ __forceinline__ void initacc(const float* bi, const float* bh, int jb,
                                        ull aR[P][2], ull aZ[P][2],
                                        ull aIN[P][2], ull aHN[P][2]) {
#pragma unroll
    for (int u = 0; u < 2; u++) {
        ull br  = splat(bi[jb + u] + bh[jb + u]);
        ull bz  = splat(bi[64 + jb + u] + bh[64 + jb + u]);
        ull bin = splat(bi[128 + jb + u]);
        ull bhn = splat(bh[128 + jb + u]);
#pragma unroll
        for (int p = 0; p < P; p++) {
            aR[p][u] = br; aZ[p][u] = bz; aIN[p][u] = bin; aHN[p][u] = bhn;
        }
    }
}

// GRU elementwise; h_new written back into aIN (reused to save regs).
template <int P>
__device__ __forceinline__ void gru_elt(const ull* Hp, int p0, int jb,
                                        ull aR[P][2], ull aZ[P][2],
                                        ull aIN[P][2], ull aHN[P][2]) {
#pragma unroll
    for (int p = 0; p < P; p++) {
#pragma unroll
        for (int u = 0; u < 2; u++) {
            float2 rr = unp(aR[p][u]);
            float2 zz = unp(aZ[p][u]);
            float2 ii = unp(aIN[p][u]);
            float2 hh = unp(aHN[p][u]);
            float2 hold = unp(Hp[(p0 + p) * HPS + jb + u]);
            float r0 = sigf(rr.x), r1 = sigf(rr.y);
            float z0 = sigf(zz.x), z1 = sigf(zz.y);
            float n0 = tanhfast(fmaf(r0, hh.x, ii.x));
            float n1 = tanhfast(fmaf(r1, hh.y, ii.y));
            float h0 = fmaf(z0, hold.x - n0, n0);
            float h1 = fmaf(z1, hold.y - n1, n1);
            aIN[p][u] = pack2(h0, h1);
        }
    }
}

template <int P>
__device__ __forceinline__ void store_tile(ull* Hp, int p0, int jb, ull hn[P][2]) {
#pragma unroll
    for (int p = 0; p < P; p++)
#pragma unroll
        for (int u = 0; u < 2; u++)
            Hp[(p0 + p) * HPS + jb + u] = hn[p][u];
}

// ================= per-warp encoder (no block barriers) =================
template <int P>
__device__ void warp_encoder(const float* __restrict__ x, float* sm,
                             int rowbase, int p0, int jb, int ug, int rg, int B) {
    float* sWhh0 = sm + OFF_WHH0;
    float* sWih1 = sm + OFF_WIH1;
    float* sWhh1 = sm + OFF_WHH1;
    float* sWih0 = sm + OFF_WIH0;
    ull* H0u = (ull*)(sm + OFF_H0);
    ull* H1u = (ull*)(sm + OFF_H1);
    const int rowoff = p0 * 2;             // warp's first local row
    const int NXV = 6 * 2 * P;             // x values per warp per t

    ull aR[P][2], aZ[P][2], aIN[P][2], aHN[P][2];

    // stage x[t=0] into buffer 0 (warp-local)
    {
        float* xb = sm + OFF_X0 + rg * 64;
#pragma unroll
        for (int s = 0; s < 2; s++) {
            int i = ug + 32 * s;
            if (i < NXV) {
                int r = i / NIn, c = i - NIn * r;
                int gr = rowbase + rowoff + r;
                float v = (gr < B) ? x[(size_t)gr * XSTR + c] : 0.0f;
                xb[((r >> 1) * XPS + c) * 2 + (r & 1)] = v;
            }
        }
        __syncwarp();
    }

    for (int t = 0; t < TENC; t++) {
        const ull* Xb = (const ull*)(sm + ((t & 1) ? OFF_X1 : OFF_X0) + rg * 64);

        // prefetch x[t+1]
        float xp[2] = {0.0f, 0.0f};
        if (t + 1 < TENC) {
#pragma unroll
            for (int s = 0; s < 2; s++) {
                int i = ug + 32 * s;
                if (i < NXV) {
                    int r = i / NIn, c = i - NIn * r;
                    int gr = rowbase + rowoff + r;
                    xp[s] = (gr < B) ? x[(size_t)gr * XSTR + (t + 1) * NIn + c] : 0.0f;
                }
            }
        }

        // layer 0
        initacc<P>(sm + OFF_B0I, sm + OFF_B0H, jb, aR, aZ, aIN, aHN);
        accumK<NIn, XPS, P>(sWih0, Xb, 0, jb, aR, aZ, aIN);
        accumK<HH, HPS, P>(sWhh0, H0u, p0, jb, aR, aZ, aHN);
        gru_elt<P>(H0u, p0, jb, aR, aZ, aIN, aHN);
        __syncwarp();
        store_tile<P>(H0u, p0, jb, aIN);
        __syncwarp();

        // layer 1
        initacc<P>(sm + OFF_B1I, sm + OFF_B1H, jb, aR, aZ, aIN, aHN);
        accumK<HH, HPS, P>(sWih1, H0u, p0, jb, aR, aZ, aIN);
        accumK<HH, HPS, P>(sWhh1, H1u, p0, jb, aR, aZ, aHN);
        gru_elt<P>(H1u, p0, jb, aR, aZ, aIN, aHN);
        __syncwarp();
        store_tile<P>(H1u, p0, jb, aIN);

        // stage prefetched x into the other warp-local buffer
        if (t + 1 < TENC) {
            float* xb = sm + (((t + 1) & 1) ? OFF_X1 : OFF_X0) + rg * 64;
#pragma unroll
            for (int s = 0; s < 2; s++) {
                int i = ug + 32 * s;
                if (i < NXV) {
                    int r = i / NIn, c = i - NIn * r;
                    xb[((r >> 1) * XPS + c) * 2 + (r & 1)] = xp[s];
                }
            }
        }
        __syncwarp();
    }
}

// ================= per-warp decoder (no block barriers) =================
template <int P>
__device__ void warp_decoder(float* sm, float* __restrict__ out,
                             int rowbase, int p0, int jb, int ug, int TL, int B) {
    float* sWhh0 = sm + OFF_WHH0;
    float* sWih1 = sm + OFF_WIH1;
    float* sWhh1 = sm + OFF_WHH1;
    float* sWih0 = sm + OFF_WIH0;
    ull* H0u = (ull*)(sm + OFF_H0);
    ull* H1u = (ull*)(sm + OFF_H1);
    float* Pvf = sm + OFF_PREV;
    const float* sHW = sm + OFF_HW;
    const float* sHb = sm + OFF_HB;
    const int rowoff = p0 * 2;

    ull aR[P][2], aZ[P][2], aIN[P][2], aHN[P][2];

    // head lane mapping: lane = hr*4 + head*2 + half
    const int hr = ug >> 2;
    const int head = (ug >> 1) & 1;
    const int half = ug & 1;
    const int hrc = (hr < 2 * P) ? hr : 0;
    const float* hf = ((const float*)H1u) + (p0 + (hrc >> 1)) * (2 * HPS) + (hrc & 1);
    const float* wv = sHW + head * 64;

    for (int t = 0; t < TL; t++) {
        // layer 0 (K=1 input = prev scalar)
        initacc<P>(sm + OFF_B0I, sm + OFF_B0H, jb, aR, aZ, aIN, aHN);
        {
            ull pv[P];
#pragma unroll
            for (int p = 0; p < P; p++) pv[p] = ((const ull*)Pvf)[p0 + p];
#pragma unroll
            for (int u = 0; u < 2; u++) {
                ull wr = splat(sWih0[jb + u]);
                ull wz = splat(sWih0[64 + jb + u]);
                ull wn = splat(sWih0[128 + jb + u]);
#pragma unroll
                for (int p = 0; p < P; p++) {
                    fma2(aR[p][u], pv[p], wr);
                    fma2(aZ[p][u], pv[p], wz);
                    fma2(aIN[p][u], pv[p], wn);
                }
            }
        }
        accumK<HH, HPS, P>(sWhh0, H0u, p0, jb, aR, aZ, aHN);
        gru_elt<P>(H0u, p0, jb, aR, aZ, aIN, aHN);
        __syncwarp();
        store_tile<P>(H0u, p0, jb, aIN);
        __syncwarp();

        // layer 1
        initacc<P>(sm + OFF_B1I, sm + OFF_B1H, jb, aR, aZ, aIN, aHN);
        accumK<HH, HPS, P>(sWih1, H0u, p0, jb, aR, aZ, aIN);
        accumK<HH, HPS, P>(sWhh1, H1u, p0, jb, aR, aZ, aHN);
        gru_elt<P>(H1u, p0, jb, aR, aZ, aIN, aHN);
        __syncwarp();
        store_tile<P>(H1u, p0, jb, aIN);
        __syncwarp();

        // heads: each (row, head) pair computed by 2 lanes (k halves), warp-local
        float acc = 0.0f;
        {
            const int k0 = half * 32;
#pragma unroll 8
            for (int k = k0; k < k0 + 32; k++)
                acc = fmaf(hf[2 * k], wv[k], acc);
        }
        acc += __shfl_xor_sync(0xffffffffu, acc, 1);        // combine k-halves
        float other = __shfl_xor_sync(0xffffffffu, acc, 2); // logit lane <- cv dot
        if (half == 0 && head == 0 && hr < 2 * P) {
            float lg = acc + sHb[0];
            float cv = other + sHb[1];
            float g = (lg > 0.0f) ? cv : 0.0f;   // sigmoid(lg) > 0.5 <=> lg > 0
            Pvf[rowoff + hr] = g;
            int grow = rowbase + rowoff + hr;
            if (grow < B) out[(size_t)grow * TL + t] = g;
        }
        __syncwarp();
    }
}

extern "C" __global__ void __launch_bounds__(NTHR, 1)
ccseq_kernel(const float* __restrict__ x, const int* __restrict__ p_tlen,
             const float* eWih0, const float* eWhh0, const float* ebih0, const float* ebhh0,
             const float* eWih1, const float* eWhh1, const float* ebih1, const float* ebhh1,
             const float* dWih0, const float* dWhh0, const float* dbih0, const float* dbhh0,
             const float* dWih1, const float* dWhh1, const float* dbih1, const float* dbhh1,
             const float* Won, const float* bon, const float* Wcv, const float* bcv,
             float* __restrict__ out, int B) {
    extern __shared__ float sm[];

    const int tid = threadIdx.x;
    const int rowbase = blockIdx.x * ROWS;
    const int ug = tid & 31;
    const int rg = tid >> 5;                  // warp id 0..19
    const int jb = ug * 2;
    // mixed tiling over 20 warps: warps 0-15 own 3 pairs, warps 16-19 own 2.
    // SMSP s (= rg & 3) gets warps {s, s+4, s+8, s+12} (P3) + {16+s} (P2)
    //   -> 3+3+3+3+2 = 14 pairs per SMSP (balanced).
    const int p0 = (rg < 16) ? rg * 3 : 48 + (rg - 16) * 2;

    // ---- encoder weights + biases, zero state ----
    loadWT(sm + OFF_WHH0, eWhh0);
    loadWT(sm + OFF_WIH1, eWih1);
    loadWT(sm + OFF_WHH1, eWhh1);
    for (int i = tid; i < NIn * 192; i += NTHR) {
        int k = i / 192, j = i - k * 192;
        sm[OFF_WIH0 + i] = eWih0[j * NIn + k];
    }
    for (int i = tid; i < 192; i += NTHR) {
        sm[OFF_B0I + i] = ebih0[i]; sm[OFF_B0H + i] = ebhh0[i];
        sm[OFF_B1I + i] = ebih1[i]; sm[OFF_B1H + i] = ebhh1[i];
    }
    for (int i = tid; i < 2 * 7280; i += NTHR) sm[OFF_H0 + i] = 0.0f;
    __syncthreads();

    const int TL = p_tlen[0];

    // ================= encoder (warp-independent) =================
    if (rg < 16) warp_encoder<3>(x, sm, rowbase, p0, jb, ug, rg, B);
    else         warp_encoder<2>(x, sm, rowbase, p0, jb, ug, rg, B);

    __syncthreads();   // all warps finished with encoder weights

    // ---- swap in decoder weights ----
    loadWT(sm + OFF_WHH0, dWhh0);
    loadWT(sm + OFF_WIH1, dWih1);
    loadWT(sm + OFF_WHH1, dWhh1);
    for (int i = tid; i < 192; i += NTHR) {
        sm[OFF_WIH0 + i] = dWih0[i];
        sm[OFF_B0I + i] = dbih0[i]; sm[OFF_B0H + i] = dbhh0[i];
        sm[OFF_B1I + i] = dbih1[i]; sm[OFF_B1H + i] = dbhh1[i];
    }
    for (int i = tid; i < HH; i += NTHR) {
        sm[OFF_HW + i] = Won[i];
        sm[OFF_HW + 64 + i] = Wcv[i];
    }
    if (tid == 0) { sm[OFF_HB] = bon[0]; sm[OFF_HB + 1] = bcv[0]; }
    for (int i = tid; i < 128; i += NTHR) sm[OFF_PREV + i] = 0.0f;
    __syncthreads();

    // ================= decoder (warp-independent) =================
    if (rg < 16) warp_decoder<3>(sm, out, rowbase, p0, jb, ug, TL, B);
    else         warp_decoder<2>(sm, out, rowbase, p0, jb, ug, TL, B);
}

extern "C" void kernel_launch(void* const* d_in, const int* in_sizes, int n_in,
                              void* d_out, int out_size) {
    const float* x     = (const float*)d_in[0];
    const int*   tlen  = (const int*)d_in[1];
    const float* eWih0 = (const float*)d_in[2];
    const float* eWhh0 = (const float*)d_in[3];
    const float* ebih0 = (const float*)d_in[4];
    const float* ebhh0 = (const float*)d_in[5];
    const float* eWih1 = (const float*)d_in[6];
    const float* eWhh1 = (const float*)d_in[7];
    const float* ebih1 = (const float*)d_in[8];
    const float* ebhh1 = (const float*)d_in[9];
    const float* dWih0 = (const float*)d_in[10];
    const float* dWhh0 = (const float*)d_in[11];
    const float* dbih0 = (const float*)d_in[12];
    const float* dbhh0 = (const float*)d_in[13];
    const float* dWih1 = (const float*)d_in[14];
    const float* dWhh1 = (const float*)d_in[15];
    const float* dbih1 = (const float*)d_in[16];
    const float* dbhh1 = (const float*)d_in[17];
    const float* Won   = (const float*)d_in[18];
    const float* bon   = (const float*)d_in[19];
    const float* Wcv   = (const float*)d_in[20];
    const float* bcv   = (const float*)d_in[21];
    float* out = (float*)d_out;

    int B = in_sizes[0] / XSTR;
    int grid = (B + ROWS - 1) / ROWS;   // 147 for B=16384

    size_t smem = (size_t)SMEM_FLOATS * sizeof(float);
    cudaFuncSetAttribute(ccseq_kernel, cudaFuncAttributeMaxDynamicSharedMemorySize, (int)smem);

    ccseq_kernel<<<grid, NTHR, smem>>>(
        x, tlen,
        eWih0, eWhh0, ebih0, ebhh0, eWih1, eWhh1, ebih1, ebhh1,
        dWih0, dWhh0, dbih0, dbhh0, dWih1, dWhh1, dbih1, dbhh1,
        Won, bon, Wcv, bcv, out, B);
}

// round 14
// speedup vs baseline: 1.6585x; 1.6585x over previous
#include <cuda_runtime.h>
#include <math.h>

#define NTHR   640
#define NW     20
#define ROWS   112               // 56 pairs: 16 warps x 3 pairs + 4 warps x 2 pairs
#define NPAIR  56
#define HH     64
#define TENC   256
#define NIn    6
#define XSTR   (TENC * NIn)
#define HPS    65     // H pair-row stride in ull units (odd -> conflict-free)
#define XPS    8      // x pair-row stride in ull units (per-warp region)

typedef unsigned long long ull;

// ---- shared layout (float offsets) ----
#define OFF_WHH0 0                  // 12288
#define OFF_WIH1 12288              // 12288
#define OFF_WHH1 24576              // 12288
#define OFF_WIH0 36864              // 1152 (enc [6][192]) / dec vector [192]
#define OFF_B0I  38016              // 192
#define OFF_B0H  38208
#define OFF_B1I  38400
#define OFF_B1H  38592
#define OFF_H0   38784              // 56*65*2 = 7280
#define OFF_H1   46064              // 7280
#define OFF_X0   53344              // 20 warps * 64 = 1280
#define OFF_X1   54624              // 1280
#define OFF_PREV 55904              // 128 floats (rows)
#define OFF_HW   56032              // 128 : [0..63]=Won, [64..127]=Wcv
#define OFF_HB   56160              // 2
#define SMEM_FLOATS 56162           // ~224.6 KB

__device__ __forceinline__ ull splat(float v) {
    ull r; asm("mov.b64 %0, {%1, %1};" : "=l"(r) : "f"(v)); return r;
}
__device__ __forceinline__ ull pack2(float a, float b) {
    ull r; asm("mov.b64 %0, {%1, %2};" : "=l"(r) : "f"(a), "f"(b)); return r;
}
__device__ __forceinline__ float2 unp(ull v) {
    float2 f; asm("mov.b64 {%0, %1}, %2;" : "=f"(f.x), "=f"(f.y) : "l"(v)); return f;
}
__device__ __forceinline__ void fma2(ull& d, ull a, ull b) {
    asm("fma.rn.f32x2 %0, %1, %2, %0;" : "+l"(d) : "l"(a), "l"(b));
}
__device__ __forceinline__ float sigf(float x) {
    return __fdividef(1.0f, 1.0f + __expf(-x));
}
__device__ __forceinline__ float tanhfast(float x) {
    float e = __expf(2.0f * x);
    return 1.0f - __fdividef(2.0f, e + 1.0f);
}

// transpose [192][64] gmem -> [64][192] smem
__device__ __forceinline__ void loadWT(float* dst, const float* __restrict__ g) {
    for (int i = threadIdx.x; i < 64 * 192; i += NTHR) {
        int k = i / 192, j = i - k * 192;
        dst[i] = g[j * 64 + k];
    }
}

// Accumulate U[pairs][K] @ W[K][192] into thread tile (P pairs x 2 units x 3 gates).
template <int K, int PSTR, int P>
__device__ __forceinline__ void accumK(const float* __restrict__ W,
                                       const ull* __restrict__ Up,
                                       int p0, int jb,
                                       ull aR[P][2], ull aZ[P][2], ull aT[P][2]) {
    const ull* h = Up + p0 * PSTR;
    const float* w = W + jb;
#pragma unroll 2
    for (int k = 0; k < K; k++) {
        ull hv[P];
#pragma unroll
        for (int p = 0; p < P; p++) hv[p] = h[p * PSTR + k];
        float2 wr = *(const float2*)w;
        float2 wz = *(const float2*)(w + 64);
        float2 wn = *(const float2*)(w + 128);
        ull wr0 = splat(wr.x), wr1 = splat(wr.y);
        ull wz0 = splat(wz.x), wz1 = splat(wz.y);
        ull wn0 = splat(wn.x), wn1 = splat(wn.y);
#pragma unroll
        for (int p = 0; p < P; p++) {
            fma2(aR[p][0], hv[p], wr0); fma2(aR[p][1], hv[p], wr1);
            fma2(aZ[p][0], hv[p], wz0); fma2(aZ[p][1], hv[p], wz1);
            fma2(aT[p][0], hv[p], wn0); fma2(aT[p][1], hv[p], wn1);
        }
        w += 192;
    }
}

template <int P>
__device__ __forceinline__ void initacc(const float* bi, const float* bh, int jb,
                                        ull aR[P][2], ull aZ[P][2],
                                        ull aIN[P][2], ull aHN[P][2]) {
#pragma unroll
    for (int u = 0; u < 2; u++) {
        ull br  = splat(bi[jb + u] + bh[jb + u]);
        ull bz  = splat(bi[64 + jb + u] + bh[64 + jb + u]);
        ull bin = splat(bi[128 + jb + u]);
        ull bhn = splat(bh[128 + jb + u]);
#pragma unroll
        for (int p = 0; p < P; p++) {
            aR[p][u] = br; aZ[p][u] = bz; aIN[p][u] = bin; aHN[p][u] = bhn;
        }
    }
}

// GRU elementwise; h_new written back into aIN (reused to save regs).
template <int P>
__device__ __forceinline__ void gru_elt(const ull* Hp, int p0, int jb,
                                        ull aR[P][2], ull aZ[P][2],
                                        ull aIN[P][2], ull aHN[P][2]) {
#pragma unroll
    for (int p = 0; p < P; p++) {
#pragma unroll
        for (int u = 0; u < 2; u++) {
            float2 rr = unp(aR[p][u]);
            float2 zz = unp(aZ[p][u]);
            float2 ii = unp(aIN[p][u]);
            float2 hh = unp(aHN[p][u]);
            float2 hold = unp(Hp[(p0 + p) * HPS + jb + u]);
            float r0 = sigf(rr.x), r1 = sigf(rr.y);
            float z0 = sigf(zz.x), z1 = sigf(zz.y);
            float n0 = tanhfast(fmaf(r0, hh.x, ii.x));
            float n1 = tanhfast(fmaf(r1, hh.y, ii.y));
            float h0 = fmaf(z0, hold.x - n0, n0);
            float h1 = fmaf(z1, hold.y - n1, n1);
            aIN[p][u] = pack2(h0, h1);
        }
    }
}

template <int P>
__device__ __forceinline__ void store_tile(ull* Hp, int p0, int jb, ull hn[P][2]) {
#pragma unroll
    for (int p = 0; p < P; p++)
#pragma unroll
        for (int u = 0; u < 2; u++)
            Hp[(p0 + p) * HPS + jb + u] = hn[p][u];
}

// ================= per-warp encoder (no block barriers) =================
template <int P>
__device__ void warp_encoder(const float* __restrict__ x, float* sm,
                             int rowbase, int p0, int jb, int ug, int rg, int B) {
    float* sWhh0 = sm + OFF_WHH0;
    float* sWih1 = sm + OFF_WIH1;
    float* sWhh1 = sm + OFF_WHH1;
    float* sWih0 = sm + OFF_WIH0;
    ull* H0u = (ull*)(sm + OFF_H0);
    ull* H1u = (ull*)(sm + OFF_H1);
    const int rowoff = p0 * 2;             // warp's first local row
    const int NXV = 6 * 2 * P;             // x values per warp per t

    ull aR[P][2], aZ[P][2], aIN[P][2], aHN[P][2];

    // stage x[t=0] into buffer 0 (warp-local)
    {
        float* xb = sm + OFF_X0 + rg * 64;
#pragma unroll
        for (int s = 0; s < 2; s++) {
            int i = ug + 32 * s;
            if (i < NXV) {
                int r = i / NIn, c = i - NIn * r;
                int gr = rowbase + rowoff + r;
                float v = (gr < B) ? x[(size_t)gr * XSTR + c] : 0.0f;
                xb[((r >> 1) * XPS + c) * 2 + (r & 1)] = v;
            }
        }
        __syncwarp();
    }

    for (int t = 0; t < TENC; t++) {
        const ull* Xb = (const ull*)(sm + ((t & 1) ? OFF_X1 : OFF_X0) + rg * 64);

        // prefetch x[t+1]
        float xp[2] = {0.0f, 0.0f};
        if (t + 1 < TENC) {
#pragma unroll
            for (int s = 0; s < 2; s++) {
                int i = ug + 32 * s;
                if (i < NXV) {
                    int r = i / NIn, c = i - NIn * r;
                    int gr = rowbase + rowoff + r;
                    xp[s] = (gr < B) ? x[(size_t)gr * XSTR + (t + 1) * NIn + c] : 0.0f;
                }
            }
        }

        // layer 0
        initacc<P>(sm + OFF_B0I, sm + OFF_B0H, jb, aR, aZ, aIN, aHN);
        accumK<NIn, XPS, P>(sWih0, Xb, 0, jb, aR, aZ, aIN);
        accumK<HH, HPS, P>(sWhh0, H0u, p0, jb, aR, aZ, aHN);
        gru_elt<P>(H0u, p0, jb, aR, aZ, aIN, aHN);
        __syncwarp();
        store_tile<P>(H0u, p0, jb, aIN);
        __syncwarp();

        // layer 1
        initacc<P>(sm + OFF_B1I, sm + OFF_B1H, jb, aR, aZ, aIN, aHN);
        accumK<HH, HPS, P>(sWih1, H0u, p0, jb, aR, aZ, aIN);
        accumK<HH, HPS, P>(sWhh1, H1u, p0, jb, aR, aZ, aHN);
        gru_elt<P>(H1u, p0, jb, aR, aZ, aIN, aHN);
        __syncwarp();
        store_tile<P>(H1u, p0, jb, aIN);

        // stage prefetched x into the other warp-local buffer
        if (t + 1 < TENC) {
            float* xb = sm + (((t + 1) & 1) ? OFF_X1 : OFF_X0) + rg * 64;
#pragma unroll
            for (int s = 0; s < 2; s++) {
                int i = ug + 32 * s;
                if (i < NXV) {
                    int r = i / NIn, c = i - NIn * r;
                    xb[((r >> 1) * XPS + c) * 2 + (r & 1)] = xp[s];
                }
            }
        }
        __syncwarp();
    }
}

// ================= per-warp decoder (no block barriers) =================
template <int P>
__device__ void warp_decoder(float* sm, float* __restrict__ out,
                             int rowbase, int p0, int jb, int ug, int TL, int B) {
    float* sWhh0 = sm + OFF_WHH0;
    float* sWih1 = sm + OFF_WIH1;
    float* sWhh1 = sm + OFF_WHH1;
    float* sWih0 = sm + OFF_WIH0;
    ull* H0u = (ull*)(sm + OFF_H0);
    ull* H1u = (ull*)(sm + OFF_H1);
    float* Pvf = sm + OFF_PREV;
    const float* sHW = sm + OFF_HW;
    const float* sHb = sm + OFF_HB;
    const int rowoff = p0 * 2;

    ull aR[P][2], aZ[P][2], aIN[P][2], aHN[P][2];

    // head lane mapping: lane = hr*4 + head*2 + half
    const int hr = ug >> 2;
    const int head = (ug >> 1) & 1;
    const int half = ug & 1;
    const int hrc = (hr < 2 * P) ? hr : 0;
    const float* hf = ((const float*)H1u) + (p0 + (hrc >> 1)) * (2 * HPS) + (hrc & 1);
    const float* wv = sHW + head * 64;

    for (int t = 0; t < TL; t++) {
        // layer 0 (K=1 input = prev scalar)
        initacc<P>(sm + OFF_B0I, sm + OFF_B0H, jb, aR, aZ, aIN, aHN);
        {
            ull pv[P];
#pragma unroll
            for (int p = 0; p < P; p++) pv[p] = ((const ull*)Pvf)[p0 + p];
#pragma unroll
            for (int u = 0; u < 2; u++) {
                ull wr = splat(sWih0[jb + u]);
                ull wz = splat(sWih0[64 + jb + u]);
                ull wn = splat(sWih0[128 + jb + u]);
#pragma unroll
                for (int p = 0; p < P; p++) {
                    fma2(aR[p][u], pv[p], wr);
                    fma2(aZ[p][u], pv[p], wz);
                    fma2(aIN[p][u], pv[p], wn);
                }
            }
        }
        accumK<HH, HPS, P>(sWhh0, H0u, p0, jb, aR, aZ, aHN);
        gru_elt<P>(H0u, p0, jb, aR, aZ, aIN, aHN);
        __syncwarp();
        store_tile<P>(H0u, p0, jb, aIN);
        __syncwarp();

        // layer 1
        initacc<P>(sm + OFF_B1I, sm + OFF_B1H, jb, aR, aZ, aIN, aHN);
        accumK<HH, HPS, P>(sWih1, H0u, p0, jb, aR, aZ, aIN);
        accumK<HH, HPS, P>(sWhh1, H1u, p0, jb, aR, aZ, aHN);
        gru_elt<P>(H1u, p0, jb, aR, aZ, aIN, aHN);
        __syncwarp();
        store_tile<P>(H1u, p0, jb, aIN);
        __syncwarp();

        // heads: each (row, head) pair computed by 2 lanes (k halves), warp-local
        float acc = 0.0f;
        {
            const int k0 = half * 32;
#pragma unroll 8
            for (int k = k0; k < k0 + 32; k++)
                acc = fmaf(hf[2 * k], wv[k], acc);
        }
        acc += __shfl_xor_sync(0xffffffffu, acc, 1);        // combine k-halves
        float other = __shfl_xor_sync(0xffffffffu, acc, 2); // logit lane <- cv dot
        if (half == 0 && head == 0 && hr < 2 * P) {
            float lg = acc + sHb[0];
            float cv = other + sHb[1];
            float g = (lg > 0.0f) ? cv : 0.0f;   // sigmoid(lg) > 0.5 <=> lg > 0
            Pvf[rowoff + hr] = g;
            int grow = rowbase + rowoff + hr;
            if (grow < B) out[(size_t)grow * TL + t] = g;
        }
        __syncwarp();
    }
}

extern "C" __global__ void __launch_bounds__(NTHR, 1)
ccseq_kernel(const float* __restrict__ x, const int* __restrict__ p_tlen,
             const float* eWih0, const float* eWhh0, const float* ebih0, const float* ebhh0,
             const float* eWih1, const float* eWhh1, const float* ebih1, const float* ebhh1,
             const float* dWih0, const float* dWhh0, const float* dbih0, const float* dbhh0,
             const float* dWih1, const float* dWhh1, const float* dbih1, const float* dbhh1,
             const float* Won, const float* bon, const float* Wcv, const float* bcv,
             float* __restrict__ out, int B) {
    extern __shared__ float sm[];

    const int tid = threadIdx.x;
    const int rowbase = blockIdx.x * ROWS;
    const int ug = tid & 31;
    const int rg = tid >> 5;                  // warp id 0..19
    const int jb = ug * 2;
    // mixed tiling over 20 warps: warps 0-15 own 3 pairs, warps 16-19 own 2.
    // SMSP s (= rg & 3) gets warps {s, s+4, s+8, s+12} (P3) + {16+s} (P2)
    //   -> 3+3+3+3+2 = 14 pairs per SMSP (balanced).
    const int p0 = (rg < 16) ? rg * 3 : 48 + (rg - 16) * 2;

    // ---- encoder weights + biases, zero state ----
    loadWT(sm + OFF_WHH0, eWhh0);
    loadWT(sm + OFF_WIH1, eWih1);
    loadWT(sm + OFF_WHH1, eWhh1);
    for (int i = tid; i < NIn * 192; i += NTHR) {
        int k = i / 192, j = i - k * 192;
        sm[OFF_WIH0 + i] = eWih0[j * NIn + k];
    }
    for (int i = tid; i < 192; i += NTHR) {
        sm[OFF_B0I + i] = ebih0[i]; sm[OFF_B0H + i] = ebhh0[i];
        sm[OFF_B1I + i] = ebih1[i]; sm[OFF_B1H + i] = ebhh1[i];
    }
    for (int i = tid; i < 2 * 7280; i += NTHR) sm[OFF_H0 + i] = 0.0f;
    __syncthreads();

    const int TL = p_tlen[0];

    // ================= encoder (warp-independent) =================
    if (rg < 16) warp_encoder<3>(x, sm, rowbase, p0, jb, ug, rg, B);
    else         warp_encoder<2>(x, sm, rowbase, p0, jb, ug, rg, B);

    __syncthreads();   // all warps finished with encoder weights

    // ---- swap in decoder weights ----
    loadWT(sm + OFF_WHH0, dWhh0);
    loadWT(sm + OFF_WIH1, dWih1);
    loadWT(sm + OFF_WHH1, dWhh1);
    for (int i = tid; i < 192; i += NTHR) {
        sm[OFF_WIH0 + i] = dWih0[i];
        sm[OFF_B0I + i] = dbih0[i]; sm[OFF_B0H + i] = dbhh0[i];
        sm[OFF_B1I + i] = dbih1[i]; sm[OFF_B1H + i] = dbhh1[i];
    }
    for (int i = tid; i < HH; i += NTHR) {
        sm[OFF_HW + i] = Won[i];
        sm[OFF_HW + 64 + i] = Wcv[i];
    }
    if (tid == 0) { sm[OFF_HB] = bon[0]; sm[OFF_HB + 1] = bcv[0]; }
    for (int i = tid; i < 128; i += NTHR) sm[OFF_PREV + i] = 0.0f;
    __syncthreads();

    // ================= decoder (warp-independent) =================
    if (rg < 16) warp_decoder<3>(sm, out, rowbase, p0, jb, ug, TL, B);
    else         warp_decoder<2>(sm, out, rowbase, p0, jb, ug, TL, B);
}

extern "C" void kernel_launch(void* const* d_in, const int* in_sizes, int n_in,
                              void* d_out, int out_size) {
    const float* x     = (const float*)d_in[0];
    const int*   tlen  = (const int*)d_in[1];
    const float* eWih0 = (const float*)d_in[2];
    const float* eWhh0 = (const float*)d_in[3];
    const float* ebih0 = (const float*)d_in[4];
    const float* ebhh0 = (const float*)d_in[5];
    const float* eWih1 = (const float*)d_in[6];
    const float* eWhh1 = (const float*)d_in[7];
    const float* ebih1 = (const float*)d_in[8];
    const float* ebhh1 = (const float*)d_in[9];
    const float* dWih0 = (const float*)d_in[10];
    const float* dWhh0 = (const float*)d_in[11];
    const float* dbih0 = (const float*)d_in[12];
    const float* dbhh0 = (const float*)d_in[13];
    const float* dWih1 = (const float*)d_in[14];
    const float* dWhh1 = (const float*)d_in[15];
    const float* dbih1 = (const float*)d_in[16];
    const float* dbhh1 = (const float*)d_in[17];
    const float* Won   = (const float*)d_in[18];
    const float* bon   = (const float*)d_in[19];
    const float* Wcv   = (const float*)d_in[20];
    const float* bcv   = (const float*)d_in[21];
    float* out = (float*)d_out;

    int B = in_sizes[0] / XSTR;
    int grid = (B + ROWS - 1) / ROWS;   // 147 for B=16384

    size_t smem = (size_t)SMEM_FLOATS * sizeof(float);
    cudaFuncSetAttribute(ccseq_kernel, cudaFuncAttributeMaxDynamicSharedMemorySize, (int)smem);

    ccseq_kernel<<<grid, NTHR, smem>>>(
        x, tlen,
        eWih0, eWhh0, ebih0, ebhh0, eWih1, eWhh1, ebih1, ebhh1,
        dWih0, dWhh0, dbih0, dbhh0, dWih1, dWhh1, dbih1, dbhh1,
        Won, bon, Wcv, bcv, out, B);
}

// round 16
// speedup vs baseline: 1.7291x; 1.0426x over previous
#include <cuda_runtime.h>
#include <math.h>

#define NTHR   512
#define NW     16
#define ROWS   112               // 56 pairs: 8 warps x 4 pairs + 8 warps x 3 pairs
#define NPAIR  56
#define HH     64
#define TENC   256
#define NIn    6
#define XSTR   (TENC * NIn)
#define HPS    65     // H pair-row stride in ull units (odd -> conflict-free)
#define XPS    8      // x pair-row stride in ull units (per-warp region)

typedef unsigned long long ull;

// ---- shared layout (float offsets) ----
#define OFF_WHH0 0                  // 12288
#define OFF_WIH1 12288              // 12288
#define OFF_WHH1 24576              // 12288
#define OFF_WIH0 36864              // 1152 (enc [6][192]) / dec vector [192]
#define OFF_B0I  38016              // 192
#define OFF_B0H  38208
#define OFF_B1I  38400
#define OFF_B1H  38592
#define OFF_H0   38784              // 56*65*2 = 7280
#define OFF_H1   46064              // 7280
#define OFF_X0   53344              // 16 warps * 64 = 1024
#define OFF_X1   54368              // 1024
#define OFF_PREV 55392              // 128 floats (rows)
#define OFF_HW   55520              // 128 : [0..63]=Won, [64..127]=Wcv
#define OFF_HB   55648              // 2
#define SMEM_FLOATS 55650           // ~222.6 KB

__device__ __forceinline__ ull splat(float v) {
    ull r; asm("mov.b64 %0, {%1, %1};" : "=l"(r) : "f"(v)); return r;
}
__device__ __forceinline__ ull pack2(float a, float b) {
    ull r; asm("mov.b64 %0, {%1, %2};" : "=l"(r) : "f"(a), "f"(b)); return r;
}
__device__ __forceinline__ float2 unp(ull v) {
    float2 f; asm("mov.b64 {%0, %1}, %2;" : "=f"(f.x), "=f"(f.y) : "l"(v)); return f;
}
__device__ __forceinline__ void fma2(ull& d, ull a, ull b) {
    asm("fma.rn.f32x2 %0, %1, %2, %0;" : "+l"(d) : "l"(a), "l"(b));
}
// HW tanh (sm_75+): single MUFU op
__device__ __forceinline__ float tanha(float x) {
    float r; asm("tanh.approx.f32 %0, %1;" : "=f"(r) : "f"(x)); return r;
}
// sigmoid(x) = 0.5 + 0.5*tanh(0.5x): 1 MUFU + 2 fma-pipe ops
__device__ __forceinline__ float sigf(float x) {
    return fmaf(0.5f, tanha(0.5f * x), 0.5f);
}

// transpose [192][64] gmem -> [64][192] smem
__device__ __forceinline__ void loadWT(float* dst, const float* __restrict__ g) {
    for (int i = threadIdx.x; i < 64 * 192; i += NTHR) {
        int k = i / 192, j = i - k * 192;
        dst[i] = g[j * 64 + k];
    }
}

// Accumulate U[pairs][K] @ W[K][192] into thread tile (P pairs x 2 units x 3 gates).
template <int K, int PSTR, int P>
__device__ __forceinline__ void accumK(const float* __restrict__ W,
                                       const ull* __restrict__ Up,
                                       int p0, int jb,
                                       ull aR[P][2], ull aZ[P][2], ull aT[P][2]) {
    const ull* h = Up + p0 * PSTR;
    const float* w = W + jb;
#pragma unroll 2
    for (int k = 0; k < K; k++) {
        ull hv[P];
#pragma unroll
        for (int p = 0; p < P; p++) hv[p] = h[p * PSTR + k];
        float2 wr = *(const float2*)w;
        float2 wz = *(const float2*)(w + 64);
        float2 wn = *(const float2*)(w + 128);
        ull wr0 = splat(wr.x), wr1 = splat(wr.y);
        ull wz0 = splat(wz.x), wz1 = splat(wz.y);
        ull wn0 = splat(wn.x), wn1 = splat(wn.y);
#pragma unroll
        for (int p = 0; p < P; p++) {
            fma2(aR[p][0], hv[p], wr0); fma2(aR[p][1], hv[p], wr1);
            fma2(aZ[p][0], hv[p], wz0); fma2(aZ[p][1], hv[p], wz1);
            fma2(aT[p][0], hv[p], wn0); fma2(aT[p][1], hv[p], wn1);
        }
        w += 192;
    }
}

template <int P>
__device__ __forceinline__ void initacc(const float* bi, const float* bh, int jb,
                                        ull aR[P][2], ull aZ[P][2],
                                        ull aIN[P][2], ull aHN[P][2]) {
#pragma unroll
    for (int u = 0; u < 2; u++) {
        ull br  = splat(bi[jb + u] + bh[jb + u]);
        ull bz  = splat(bi[64 + jb + u] + bh[64 + jb + u]);
        ull bin = splat(bi[128 + jb + u]);
        ull bhn = splat(bh[128 + jb + u]);
#pragma unroll
        for (int p = 0; p < P; p++) {
            aR[p][u] = br; aZ[p][u] = bz; aIN[p][u] = bin; aHN[p][u] = bhn;
        }
    }
}

// GRU elementwise; h_new written back into aIN (reused to save regs).
template <int P>
__device__ __forceinline__ void gru_elt(const ull* Hp, int p0, int jb,
                                        ull aR[P][2], ull aZ[P][2],
                                        ull aIN[P][2], ull aHN[P][2]) {
#pragma unroll
    for (int p = 0; p < P; p++) {
#pragma unroll
        for (int u = 0; u < 2; u++) {
            float2 rr = unp(aR[p][u]);
            float2 zz = unp(aZ[p][u]);
            float2 ii = unp(aIN[p][u]);
            float2 hh = unp(aHN[p][u]);
            float2 hold = unp(Hp[(p0 + p) * HPS + jb + u]);
            float r0 = sigf(rr.x), r1 = sigf(rr.y);
            float z0 = sigf(zz.x), z1 = sigf(zz.y);
            float n0 = tanha(fmaf(r0, hh.x, ii.x));
            float n1 = tanha(fmaf(r1, hh.y, ii.y));
            float h0 = fmaf(z0, hold.x - n0, n0);
            float h1 = fmaf(z1, hold.y - n1, n1);
            aIN[p][u] = pack2(h0, h1);
        }
    }
}

template <int P>
__device__ __forceinline__ void store_tile(ull* Hp, int p0, int jb, ull hn[P][2]) {
#pragma unroll
    for (int p = 0; p < P; p++)
#pragma unroll
        for (int u = 0; u < 2; u++)
            Hp[(p0 + p) * HPS + jb + u] = hn[p][u];
}

// ================= per-warp encoder (no block barriers) =================
template <int P>
__device__ void warp_encoder(const float* __restrict__ x, float* sm,
                             int rowbase, int p0, int jb, int ug, int rg, int B) {
    float* sWhh0 = sm + OFF_WHH0;
    float* sWih1 = sm + OFF_WIH1;
    float* sWhh1 = sm + OFF_WHH1;
    float* sWih0 = sm + OFF_WIH0;
    ull* H0u = (ull*)(sm + OFF_H0);
    ull* H1u = (ull*)(sm + OFF_H1);
    const int rowoff = p0 * 2;             // warp's first local row
    const int NXV = 6 * 2 * P;             // x values per warp per t

    ull aR[P][2], aZ[P][2], aIN[P][2], aHN[P][2];

    // stage x[t=0] into buffer 0 (warp-local)
    {
        float* xb = sm + OFF_X0 + rg * 64;
#pragma unroll
        for (int s = 0; s < 2; s++) {
            int i = ug + 32 * s;
            if (i < NXV) {
                int r = i / NIn, c = i - NIn * r;
                int gr = rowbase + rowoff + r;
                float v = (gr < B) ? x[(size_t)gr * XSTR + c] : 0.0f;
                xb[((r >> 1) * XPS + c) * 2 + (r & 1)] = v;
            }
        }
        __syncwarp();
    }

    for (int t = 0; t < TENC; t++) {
        const ull* Xb = (const ull*)(sm + ((t & 1) ? OFF_X1 : OFF_X0) + rg * 64);

        // prefetch x[t+1]
        float xp[2] = {0.0f, 0.0f};
        if (t + 1 < TENC) {
#pragma unroll
            for (int s = 0; s < 2; s++) {
                int i = ug + 32 * s;
                if (i < NXV) {
                    int r = i / NIn, c = i - NIn * r;
                    int gr = rowbase + rowoff + r;
                    xp[s] = (gr < B) ? x[(size_t)gr * XSTR + (t + 1) * NIn + c] : 0.0f;
                }
            }
        }

        // layer 0
        initacc<P>(sm + OFF_B0I, sm + OFF_B0H, jb, aR, aZ, aIN, aHN);
        accumK<NIn, XPS, P>(sWih0, Xb, 0, jb, aR, aZ, aIN);
        accumK<HH, HPS, P>(sWhh0, H0u, p0, jb, aR, aZ, aHN);
        gru_elt<P>(H0u, p0, jb, aR, aZ, aIN, aHN);
        __syncwarp();
        store_tile<P>(H0u, p0, jb, aIN);
        __syncwarp();

        // layer 1
        initacc<P>(sm + OFF_B1I, sm + OFF_B1H, jb, aR, aZ, aIN, aHN);
        accumK<HH, HPS, P>(sWih1, H0u, p0, jb, aR, aZ, aIN);
        accumK<HH, HPS, P>(sWhh1, H1u, p0, jb, aR, aZ, aHN);
        gru_elt<P>(H1u, p0, jb, aR, aZ, aIN, aHN);
        __syncwarp();
        store_tile<P>(H1u, p0, jb, aIN);

        // stage prefetched x into the other warp-local buffer
        if (t + 1 < TENC) {
            float* xb = sm + (((t + 1) & 1) ? OFF_X1 : OFF_X0) + rg * 64;
#pragma unroll
            for (int s = 0; s < 2; s++) {
                int i = ug + 32 * s;
                if (i < NXV) {
                    int r = i / NIn, c = i - NIn * r;
                    xb[((r >> 1) * XPS + c) * 2 + (r & 1)] = xp[s];
                }
            }
        }
        __syncwarp();
    }
}

// ================= per-warp decoder (no block barriers) =================
template <int P>
__device__ void warp_decoder(float* sm, float* __restrict__ out,
                             int rowbase, int p0, int jb, int ug, int TL, int B) {
    float* sWhh0 = sm + OFF_WHH0;
    float* sWih1 = sm + OFF_WIH1;
    float* sWhh1 = sm + OFF_WHH1;
    float* sWih0 = sm + OFF_WIH0;
    ull* H0u = (ull*)(sm + OFF_H0);
    ull* H1u = (ull*)(sm + OFF_H1);
    float* Pvf = sm + OFF_PREV;
    const float* sHW = sm + OFF_HW;
    const float* sHb = sm + OFF_HB;
    const int rowoff = p0 * 2;

    ull aR[P][2], aZ[P][2], aIN[P][2], aHN[P][2];

    // head lane mapping: lane = hr*4 + head*2 + half
    const int hr = ug >> 2;
    const int head = (ug >> 1) & 1;
    const int half = ug & 1;
    const int hrc = (hr < 2 * P) ? hr : 0;
    const float* hf = ((const float*)H1u) + (p0 + (hrc >> 1)) * (2 * HPS) + (hrc & 1);
    const float* wv = sHW + head * 64;

    for (int t = 0; t < TL; t++) {
        // layer 0 (K=1 input = prev scalar)
        initacc<P>(sm + OFF_B0I, sm + OFF_B0H, jb, aR, aZ, aIN, aHN);
        {
            ull pv[P];
#pragma unroll
            for (int p = 0; p < P; p++) pv[p] = ((const ull*)Pvf)[p0 + p];
#pragma unroll
            for (int u = 0; u < 2; u++) {
                ull wr = splat(sWih0[jb + u]);
                ull wz = splat(sWih0[64 + jb + u]);
                ull wn = splat(sWih0[128 + jb + u]);
#pragma unroll
                for (int p = 0; p < P; p++) {
                    fma2(aR[p][u], pv[p], wr);
                    fma2(aZ[p][u], pv[p], wz);
                    fma2(aIN[p][u], pv[p], wn);
                }
            }
        }
        accumK<HH, HPS, P>(sWhh0, H0u, p0, jb, aR, aZ, aHN);
        gru_elt<P>(H0u, p0, jb, aR, aZ, aIN, aHN);
        __syncwarp();
        store_tile<P>(H0u, p0, jb, aIN);
        __syncwarp();

        // layer 1
        initacc<P>(sm + OFF_B1I, sm + OFF_B1H, jb, aR, aZ, aIN, aHN);
        accumK<HH, HPS, P>(sWih1, H0u, p0, jb, aR, aZ, aIN);
        accumK<HH, HPS, P>(sWhh1, H1u, p0, jb, aR, aZ, aHN);
        gru_elt<P>(H1u, p0, jb, aR, aZ, aIN, aHN);
        __syncwarp();
        store_tile<P>(H1u, p0, jb, aIN);
        __syncwarp();

        // heads: each (row, head) pair computed by 2 lanes (k halves), warp-local
        float acc = 0.0f;
        {
            const int k0 = half * 32;
#pragma unroll 8
            for (int k = k0; k < k0 + 32; k++)
                acc = fmaf(hf[2 * k], wv[k], acc);
        }
        acc += __shfl_xor_sync(0xffffffffu, acc, 1);        // combine k-halves
        float other = __shfl_xor_sync(0xffffffffu, acc, 2); // logit lane <- cv dot
        if (half == 0 && head == 0 && hr < 2 * P) {
            float lg = acc + sHb[0];
            float cv = other + sHb[1];
            float g = (lg > 0.0f) ? cv : 0.0f;   // sigmoid(lg) > 0.5 <=> lg > 0
            Pvf[rowoff + hr] = g;
            int grow = rowbase + rowoff + hr;
            if (grow < B) out[(size_t)grow * TL + t] = g;
        }
        __syncwarp();
    }
}

extern "C" __global__ void __launch_bounds__(NTHR, 1)
ccseq_kernel(const float* __restrict__ x, const int* __restrict__ p_tlen,
             const float* eWih0, const float* eWhh0, const float* ebih0, const float* ebhh0,
             const float* eWih1, const float* eWhh1, const float* ebih1, const float* ebhh1,
             const float* dWih0, const float* dWhh0, const float* dbih0, const float* dbhh0,
             const float* dWih1, const float* dWhh1, const float* dbih1, const float* dbhh1,
             const float* Won, const float* bon, const float* Wcv, const float* bcv,
             float* __restrict__ out, int B) {
    extern __shared__ float sm[];

    const int tid = threadIdx.x;
    const int rowbase = blockIdx.x * ROWS;
    const int ug = tid & 31;
    const int rg = tid >> 5;                  // warp id 0..15
    const int jb = ug * 2;
    // mixed tiling: warps 0-7 own 4 pairs, warps 8-15 own 3 pairs.
    // SMSP s gets warps {s, s+4, s+8, s+12} = 4+4+3+3 = 14 pairs (balanced).
    const int p0 = (rg < 8) ? rg * 4 : 32 + (rg - 8) * 3;

    // ---- encoder weights + biases, zero state ----
    loadWT(sm + OFF_WHH0, eWhh0);
    loadWT(sm + OFF_WIH1, eWih1);
    loadWT(sm + OFF_WHH1, eWhh1);
    for (int i = tid; i < NIn * 192; i += NTHR) {
        int k = i / 192, j = i - k * 192;
        sm[OFF_WIH0 + i] = eWih0[j * NIn + k];
    }
    for (int i = tid; i < 192; i += NTHR) {
        sm[OFF_B0I + i] = ebih0[i]; sm[OFF_B0H + i] = ebhh0[i];
        sm[OFF_B1I + i] = ebih1[i]; sm[OFF_B1H + i] = ebhh1[i];
    }
    for (int i = tid; i < 2 * 7280; i += NTHR) sm[OFF_H0 + i] = 0.0f;
    __syncthreads();

    const int TL = p_tlen[0];

    // ================= encoder (warp-independent) =================
    if (rg < 8) warp_encoder<4>(x, sm, rowbase, p0, jb, ug, rg, B);
    else        warp_encoder<3>(x, sm, rowbase, p0, jb, ug, rg, B);

    __syncthreads();   // all warps finished with encoder weights

    // ---- swap in decoder weights ----
    loadWT(sm + OFF_WHH0, dWhh0);
    loadWT(sm + OFF_WIH1, dWih1);
    loadWT(sm + OFF_WHH1, dWhh1);
    for (int i = tid; i < 192; i += NTHR) {
        sm[OFF_WIH0 + i] = dWih0[i];
        sm[OFF_B0I + i] = dbih0[i]; sm[OFF_B0H + i] = dbhh0[i];
        sm[OFF_B1I + i] = dbih1[i]; sm[OFF_B1H + i] = dbhh1[i];
    }
    for (int i = tid; i < HH; i += NTHR) {
        sm[OFF_HW + i] = Won[i];
        sm[OFF_HW + 64 + i] = Wcv[i];
    }
    if (tid == 0) { sm[OFF_HB] = bon[0]; sm[OFF_HB + 1] = bcv[0]; }
    for (int i = tid; i < 128; i += NTHR) sm[OFF_PREV + i] = 0.0f;
    __syncthreads();

    // ================= decoder (warp-independent) =================
    if (rg < 8) warp_decoder<4>(sm, out, rowbase, p0, jb, ug, TL, B);
    else        warp_decoder<3>(sm, out, rowbase, p0, jb, ug, TL, B);
}

extern "C" void kernel_launch(void* const* d_in, const int* in_sizes, int n_in,
                              void* d_out, int out_size) {
    const float* x     = (const float*)d_in[0];
    const int*   tlen  = (const int*)d_in[1];
    const float* eWih0 = (const float*)d_in[2];
    const float* eWhh0 = (const float*)d_in[3];
    const float* ebih0 = (const float*)d_in[4];
    const float* ebhh0 = (const float*)d_in[5];
    const float* eWih1 = (const float*)d_in[6];
    const float* eWhh1 = (const float*)d_in[7];
    const float* ebih1 = (const float*)d_in[8];
    const float* ebhh1 = (const float*)d_in[9];
    const float* dWih0 = (const float*)d_in[10];
    const float* dWhh0 = (const float*)d_in[11];
    const float* dbih0 = (const float*)d_in[12];
    const float* dbhh0 = (const float*)d_in[13];
    const float* dWih1 = (const float*)d_in[14];
    const float* dWhh1 = (const float*)d_in[15];
    const float* dbih1 = (const float*)d_in[16];
    const float* dbhh1 = (const float*)d_in[17];
    const float* Won   = (const float*)d_in[18];
    const float* bon   = (const float*)d_in[19];
    const float* Wcv   = (const float*)d_in[20];
    const float* bcv   = (const float*)d_in[21];
    float* out = (float*)d_out;

    int B = in_sizes[0] / XSTR;
    int grid = (B + ROWS - 1) / ROWS;   // 147 for B=16384

    size_t smem = (size_t)SMEM_FLOATS * sizeof(float);
    cudaFuncSetAttribute(ccseq_kernel, cudaFuncAttributeMaxDynamicSharedMemorySize, (int)smem);

    ccseq_kernel<<<grid, NTHR, smem>>>(
        x, tlen,
        eWih0, eWhh0, ebih0, ebhh0, eWih1, eWhh1, ebih1, ebhh1,
        dWih0, dWhh0, dbih0, dbhh0, dWih1, dWhh1, dbih1, dbhh1,
        Won, bon, Wcv, bcv, out, B);
}

// round 17
// speedup vs baseline: 1.8085x; 1.0459x over previous
#include <cuda_runtime.h>
#include <math.h>

#define NTHR   512
#define NW     16
#define ROWS   112               // 56 pairs: 8 warps x 4 pairs + 8 warps x 3 pairs
#define NPAIR  56
#define HH     64
#define TENC   256
#define NIn    6
#define XSTR   (TENC * NIn)
#define HPS    65     // H pair-row stride in ull units (odd -> conflict-free)
#define XPS    8      // x pair-row stride in ull units (per-warp region)

typedef unsigned long long ull;

// ---- shared layout (float offsets) ----
#define OFF_WHH0 0                  // 12288
#define OFF_WIH1 12288              // 12288
#define OFF_WHH1 24576              // 12288
#define OFF_WIH0 36864              // 1152 (enc [6][192]) / dec vector [192]
#define OFF_B0I  38016              // 192
#define OFF_B0H  38208
#define OFF_B1I  38400
#define OFF_B1H  38592
#define OFF_H0   38784              // 56*65*2 = 7280
#define OFF_H1   46064              // 7280
#define OFF_X0   53344              // 16 warps * 64 = 1024
#define OFF_X1   54368              // 1024
#define OFF_PREV 55392              // 128 floats (rows)
#define OFF_HW   55520              // 128 : [0..63]=Won, [64..127]=Wcv
#define OFF_HB   55648              // 2
#define SMEM_FLOATS 55650           // ~222.6 KB

__device__ __forceinline__ ull splat(float v) {
    ull r; asm("mov.b64 %0, {%1, %1};" : "=l"(r) : "f"(v)); return r;
}
__device__ __forceinline__ ull pack2(float a, float b) {
    ull r; asm("mov.b64 %0, {%1, %2};" : "=l"(r) : "f"(a), "f"(b)); return r;
}
__device__ __forceinline__ float2 unp(ull v) {
    float2 f; asm("mov.b64 {%0, %1}, %2;" : "=f"(f.x), "=f"(f.y) : "l"(v)); return f;
}
__device__ __forceinline__ void fma2(ull& d, ull a, ull b) {
    asm("fma.rn.f32x2 %0, %1, %2, %0;" : "+l"(d) : "l"(a), "l"(b));
}
// HW tanh (sm_75+): single MUFU op
__device__ __forceinline__ float tanha(float x) {
    float r; asm("tanh.approx.f32 %0, %1;" : "=f"(r) : "f"(x)); return r;
}
// sigmoid(x) = 0.5 + 0.5*tanh(0.5x): 1 MUFU + 2 fma-pipe ops
__device__ __forceinline__ float sigf(float x) {
    return fmaf(0.5f, tanha(0.5f * x), 0.5f);
}

// transpose [192][64] gmem -> [64][192] smem
__device__ __forceinline__ void loadWT(float* dst, const float* __restrict__ g) {
    for (int i = threadIdx.x; i < 64 * 192; i += NTHR) {
        int k = i / 192, j = i - k * 192;
        dst[i] = g[j * 64 + k];
    }
}

// Accumulate U[pairs][K] @ W[K][192] into thread tile (P pairs x 2 units x 3 gates).
template <int K, int PSTR, int P>
__device__ __forceinline__ void accumK(const float* __restrict__ W,
                                       const ull* __restrict__ Up,
                                       int p0, int jb,
                                       ull aR[P][2], ull aZ[P][2], ull aT[P][2]) {
    const ull* h = Up + p0 * PSTR;
    const float* w = W + jb;
#pragma unroll 4
    for (int k = 0; k < K; k++) {
        ull hv[P];
#pragma unroll
        for (int p = 0; p < P; p++) hv[p] = h[p * PSTR + k];
        float2 wr = *(const float2*)w;
        float2 wz = *(const float2*)(w + 64);
        float2 wn = *(const float2*)(w + 128);
        ull wr0 = splat(wr.x), wr1 = splat(wr.y);
        ull wz0 = splat(wz.x), wz1 = splat(wz.y);
        ull wn0 = splat(wn.x), wn1 = splat(wn.y);
#pragma unroll
        for (int p = 0; p < P; p++) {
            fma2(aR[p][0], hv[p], wr0); fma2(aR[p][1], hv[p], wr1);
            fma2(aZ[p][0], hv[p], wz0); fma2(aZ[p][1], hv[p], wz1);
            fma2(aT[p][0], hv[p], wn0); fma2(aT[p][1], hv[p], wn1);
        }
        w += 192;
    }
}

template <int P>
__device__ __forceinline__ void initacc(const float* bi, const float* bh, int jb,
                                        ull aR[P][2], ull aZ[P][2],
                                        ull aIN[P][2], ull aHN[P][2]) {
#pragma unroll
    for (int u = 0; u < 2; u++) {
        ull br  = splat(bi[jb + u] + bh[jb + u]);
        ull bz  = splat(bi[64 + jb + u] + bh[64 + jb + u]);
        ull bin = splat(bi[128 + jb + u]);
        ull bhn = splat(bh[128 + jb + u]);
#pragma unroll
        for (int p = 0; p < P; p++) {
            aR[p][u] = br; aZ[p][u] = bz; aIN[p][u] = bin; aHN[p][u] = bhn;
        }
    }
}

// GRU elementwise; h_new written back into aIN (reused to save regs).
template <int P>
__device__ __forceinline__ void gru_elt(const ull* Hp, int p0, int jb,
                                        ull aR[P][2], ull aZ[P][2],
                                        ull aIN[P][2], ull aHN[P][2]) {
#pragma unroll
    for (int p = 0; p < P; p++) {
#pragma unroll
        for (int u = 0; u < 2; u++) {
            float2 rr = unp(aR[p][u]);
            float2 zz = unp(aZ[p][u]);
            float2 ii = unp(aIN[p][u]);
            float2 hh = unp(aHN[p][u]);
            float2 hold = unp(Hp[(p0 + p) * HPS + jb + u]);
            float r0 = sigf(rr.x), r1 = sigf(rr.y);
            float z0 = sigf(zz.x), z1 = sigf(zz.y);
            float n0 = tanha(fmaf(r0, hh.x, ii.x));
            float n1 = tanha(fmaf(r1, hh.y, ii.y));
            float h0 = fmaf(z0, hold.x - n0, n0);
            float h1 = fmaf(z1, hold.y - n1, n1);
            aIN[p][u] = pack2(h0, h1);
        }
    }
}

template <int P>
__device__ __forceinline__ void store_tile(ull* Hp, int p0, int jb, ull hn[P][2]) {
#pragma unroll
    for (int p = 0; p < P; p++)
#pragma unroll
        for (int u = 0; u < 2; u++)
            Hp[(p0 + p) * HPS + jb + u] = hn[p][u];
}

// ================= per-warp encoder (no block barriers) =================
// All steady-state smem dependencies are same-warp; the per-warp in-order MIO
// queue guarantees program-order smem visibility (incl. cross-lane), so no
// __syncwarp is needed inside the step loop.
template <int P>
__device__ void warp_encoder(const float* __restrict__ x, float* sm,
                             int rowbase, int p0, int jb, int ug, int rg, int B) {
    float* sWhh0 = sm + OFF_WHH0;
    float* sWih1 = sm + OFF_WIH1;
    float* sWhh1 = sm + OFF_WHH1;
    float* sWih0 = sm + OFF_WIH0;
    ull* H0u = (ull*)(sm + OFF_H0);
    ull* H1u = (ull*)(sm + OFF_H1);
    const int rowoff = p0 * 2;             // warp's first local row
    const int NXV = 6 * 2 * P;             // x values per warp per t

    ull aR[P][2], aZ[P][2], aIN[P][2], aHN[P][2];

    // stage x[t=0] into buffer 0 (warp-local)
    {
        float* xb = sm + OFF_X0 + rg * 64;
#pragma unroll
        for (int s = 0; s < 2; s++) {
            int i = ug + 32 * s;
            if (i < NXV) {
                int r = i / NIn, c = i - NIn * r;
                int gr = rowbase + rowoff + r;
                float v = (gr < B) ? x[(size_t)gr * XSTR + c] : 0.0f;
                xb[((r >> 1) * XPS + c) * 2 + (r & 1)] = v;
            }
        }
    }

    for (int t = 0; t < TENC; t++) {
        const ull* Xb = (const ull*)(sm + ((t & 1) ? OFF_X1 : OFF_X0) + rg * 64);

        // prefetch x[t+1]
        float xp[2] = {0.0f, 0.0f};
        if (t + 1 < TENC) {
#pragma unroll
            for (int s = 0; s < 2; s++) {
                int i = ug + 32 * s;
                if (i < NXV) {
                    int r = i / NIn, c = i - NIn * r;
                    int gr = rowbase + rowoff + r;
                    xp[s] = (gr < B) ? x[(size_t)gr * XSTR + (t + 1) * NIn + c] : 0.0f;
                }
            }
        }

        // layer 0
        initacc<P>(sm + OFF_B0I, sm + OFF_B0H, jb, aR, aZ, aIN, aHN);
        accumK<NIn, XPS, P>(sWih0, Xb, 0, jb, aR, aZ, aIN);
        accumK<HH, HPS, P>(sWhh0, H0u, p0, jb, aR, aZ, aHN);
        gru_elt<P>(H0u, p0, jb, aR, aZ, aIN, aHN);
        store_tile<P>(H0u, p0, jb, aIN);

        // layer 1: hh first (reads H1, untouched) to hide the H0 store->load
        // turnaround behind ~170 cycles of independent FMA work.
        initacc<P>(sm + OFF_B1I, sm + OFF_B1H, jb, aR, aZ, aIN, aHN);
        accumK<HH, HPS, P>(sWhh1, H1u, p0, jb, aR, aZ, aHN);
        accumK<HH, HPS, P>(sWih1, H0u, p0, jb, aR, aZ, aIN);
        gru_elt<P>(H1u, p0, jb, aR, aZ, aIN, aHN);
        store_tile<P>(H1u, p0, jb, aIN);

        // stage prefetched x into the other warp-local buffer
        if (t + 1 < TENC) {
            float* xb = sm + (((t + 1) & 1) ? OFF_X1 : OFF_X0) + rg * 64;
#pragma unroll
            for (int s = 0; s < 2; s++) {
                int i = ug + 32 * s;
                if (i < NXV) {
                    int r = i / NIn, c = i - NIn * r;
                    xb[((r >> 1) * XPS + c) * 2 + (r & 1)] = xp[s];
                }
            }
        }
    }
}

// ================= per-warp decoder (no block barriers) =================
template <int P>
__device__ void warp_decoder(float* sm, float* __restrict__ out,
                             int rowbase, int p0, int jb, int ug, int TL, int B) {
    float* sWhh0 = sm + OFF_WHH0;
    float* sWih1 = sm + OFF_WIH1;
    float* sWhh1 = sm + OFF_WHH1;
    float* sWih0 = sm + OFF_WIH0;
    ull* H0u = (ull*)(sm + OFF_H0);
    ull* H1u = (ull*)(sm + OFF_H1);
    float* Pvf = sm + OFF_PREV;
    const float* sHW = sm + OFF_HW;
    const float* sHb = sm + OFF_HB;
    const int rowoff = p0 * 2;

    ull aR[P][2], aZ[P][2], aIN[P][2], aHN[P][2];

    // head lane mapping: lane = hr*4 + head*2 + half
    const int hr = ug >> 2;
    const int head = (ug >> 1) & 1;
    const int half = ug & 1;
    const int hrc = (hr < 2 * P) ? hr : 0;
    const float* hf = ((const float*)H1u) + (p0 + (hrc >> 1)) * (2 * HPS) + (hrc & 1);
    const float* wv = sHW + head * 64;

    for (int t = 0; t < TL; t++) {
        // layer 0 (K=1 input = prev scalar)
        initacc<P>(sm + OFF_B0I, sm + OFF_B0H, jb, aR, aZ, aIN, aHN);
        {
            ull pv[P];
#pragma unroll
            for (int p = 0; p < P; p++) pv[p] = ((const ull*)Pvf)[p0 + p];
#pragma unroll
            for (int u = 0; u < 2; u++) {
                ull wr = splat(sWih0[jb + u]);
                ull wz = splat(sWih0[64 + jb + u]);
                ull wn = splat(sWih0[128 + jb + u]);
#pragma unroll
                for (int p = 0; p < P; p++) {
                    fma2(aR[p][u], pv[p], wr);
                    fma2(aZ[p][u], pv[p], wz);
                    fma2(aIN[p][u], pv[p], wn);
                }
            }
        }
        accumK<HH, HPS, P>(sWhh0, H0u, p0, jb, aR, aZ, aHN);
        gru_elt<P>(H0u, p0, jb, aR, aZ, aIN, aHN);
        store_tile<P>(H0u, p0, jb, aIN);

        // layer 1: hh first (reads H1), then ih (reads fresh H0)
        initacc<P>(sm + OFF_B1I, sm + OFF_B1H, jb, aR, aZ, aIN, aHN);
        accumK<HH, HPS, P>(sWhh1, H1u, p0, jb, aR, aZ, aHN);
        accumK<HH, HPS, P>(sWih1, H0u, p0, jb, aR, aZ, aIN);
        gru_elt<P>(H1u, p0, jb, aR, aZ, aIN, aHN);
        store_tile<P>(H1u, p0, jb, aIN);

        // heads: each (row, head) pair computed by 2 lanes (k halves), warp-local
        float acc = 0.0f;
        {
            const int k0 = half * 32;
#pragma unroll 8
            for (int k = k0; k < k0 + 32; k++)
                acc = fmaf(hf[2 * k], wv[k], acc);
        }
        acc += __shfl_xor_sync(0xffffffffu, acc, 1);        // combine k-halves
        float other = __shfl_xor_sync(0xffffffffu, acc, 2); // logit lane <- cv dot
        if (half == 0 && head == 0 && hr < 2 * P) {
            float lg = acc + sHb[0];
            float cv = other + sHb[1];
            float g = (lg > 0.0f) ? cv : 0.0f;   // sigmoid(lg) > 0.5 <=> lg > 0
            Pvf[rowoff + hr] = g;
            int grow = rowbase + rowoff + hr;
            if (grow < B) out[(size_t)grow * TL + t] = g;
        }
        __syncwarp();   // reconverge + order Pvf for next step's cross-lane reads
    }
}

extern "C" __global__ void __launch_bounds__(NTHR, 1)
ccseq_kernel(const float* __restrict__ x, const int* __restrict__ p_tlen,
             const float* eWih0, const float* eWhh0, const float* ebih0, const float* ebhh0,
             const float* eWih1, const float* eWhh1, const float* ebih1, const float* ebhh1,
             const float* dWih0, const float* dWhh0, const float* dbih0, const float* dbhh0,
             const float* dWih1, const float* dWhh1, const float* dbih1, const float* dbhh1,
             const float* Won, const float* bon, const float* Wcv, const float* bcv,
             float* __restrict__ out, int B) {
    extern __shared__ float sm[];

    const int tid = threadIdx.x;
    const int rowbase = blockIdx.x * ROWS;
    const int ug = tid & 31;
    const int rg = tid >> 5;                  // warp id 0..15
    const int jb = ug * 2;
    // mixed tiling: warps 0-7 own 4 pairs, warps 8-15 own 3 pairs.
    // SMSP s gets warps {s, s+4, s+8, s+12} = 4+4+3+3 = 14 pairs (balanced).
    const int p0 = (rg < 8) ? rg * 4 : 32 + (rg - 8) * 3;

    // ---- encoder weights + biases, zero state ----
    loadWT(sm + OFF_WHH0, eWhh0);
    loadWT(sm + OFF_WIH1, eWih1);
    loadWT(sm + OFF_WHH1, eWhh1);
    for (int i = tid; i < NIn * 192; i += NTHR) {
        int k = i / 192, j = i - k * 192;
        sm[OFF_WIH0 + i] = eWih0[j * NIn + k];
    }
    for (int i = tid; i < 192; i += NTHR) {
        sm[OFF_B0I + i] = ebih0[i]; sm[OFF_B0H + i] = ebhh0[i];
        sm[OFF_B1I + i] = ebih1[i]; sm[OFF_B1H + i] = ebhh1[i];
    }
    for (int i = tid; i < 2 * 7280; i += NTHR) sm[OFF_H0 + i] = 0.0f;
    __syncthreads();

    const int TL = p_tlen[0];

    // ================= encoder (warp-independent) =================
    if (rg < 8) warp_encoder<4>(x, sm, rowbase, p0, jb, ug, rg, B);
    else        warp_encoder<3>(x, sm, rowbase, p0, jb, ug, rg, B);

    __syncthreads();   // all warps finished with encoder weights

    // ---- swap in decoder weights ----
    loadWT(sm + OFF_WHH0, dWhh0);
    loadWT(sm + OFF_WIH1, dWih1);
    loadWT(sm + OFF_WHH1, dWhh1);
    for (int i = tid; i < 192; i += NTHR) {
        sm[OFF_WIH0 + i] = dWih0[i];
        sm[OFF_B0I + i] = dbih0[i]; sm[OFF_B0H + i] = dbhh0[i];
        sm[OFF_B1I + i] = dbih1[i]; sm[OFF_B1H + i] = dbhh1[i];
    }
    for (int i = tid; i < HH; i += NTHR) {
        sm[OFF_HW + i] = Won[i];
        sm[OFF_HW + 64 + i] = Wcv[i];
    }
    if (tid == 0) { sm[OFF_HB] = bon[0]; sm[OFF_HB + 1] = bcv[0]; }
    for (int i = tid; i < 128; i += NTHR) sm[OFF_PREV + i] = 0.0f;
    __syncthreads();

    // ================= decoder (warp-independent) =================
    if (rg < 8) warp_decoder<4>(sm, out, rowbase, p0, jb, ug, TL, B);
    else        warp_decoder<3>(sm, out, rowbase, p0, jb, ug, TL, B);
}

extern "C" void kernel_launch(void* const* d_in, const int* in_sizes, int n_in,
                              void* d_out, int out_size) {
    const float* x     = (const float*)d_in[0];
    const int*   tlen  = (const int*)d_in[1];
    const float* eWih0 = (const float*)d_in[2];
    const float* eWhh0 = (const float*)d_in[3];
    const float* ebih0 = (const float*)d_in[4];
    const float* ebhh0 = (const float*)d_in[5];
    const float* eWih1 = (const float*)d_in[6];
    const float* eWhh1 = (const float*)d_in[7];
    const float* ebih1 = (const float*)d_in[8];
    const float* ebhh1 = (const float*)d_in[9];
    const float* dWih0 = (const float*)d_in[10];
    const float* dWhh0 = (const float*)d_in[11];
    const float* dbih0 = (const float*)d_in[12];
    const float* dbhh0 = (const float*)d_in[13];
    const float* dWih1 = (const float*)d_in[14];
    const float* dWhh1 = (const float*)d_in[15];
    const float* dbih1 = (const float*)d_in[16];
    const float* dbhh1 = (const float*)d_in[17];
    const float* Won   = (const float*)d_in[18];
    const float* bon   = (const float*)d_in[19];
    const float* Wcv   = (const float*)d_in[20];
    const float* bcv   = (const float*)d_in[21];
    float* out = (float*)d_out;

    int B = in_sizes[0] / XSTR;
    int grid = (B + ROWS - 1) / ROWS;   // 147 for B=16384

    size_t smem = (size_t)SMEM_FLOATS * sizeof(float);
    cudaFuncSetAttribute(ccseq_kernel, cudaFuncAttributeMaxDynamicSharedMemorySize, (int)smem);

    ccseq_kernel<<<grid, NTHR, smem>>>(
        x, tlen,
        eWih0, eWhh0, ebih0, ebhh0, eWih1, eWhh1, ebih1, ebhh1,
        dWih0, dWhh0, dbih0, dbhh0, dWih1, dWhh1, dbih1, dbhh1,
        Won, bon, Wcv, bcv, out, B);
}